// round 4
// baseline (speedup 1.0000x reference)
#include <cuda_runtime.h>
#include <math.h>

#define Bz 256
#define Tt 25
#define Ee 353
#define Hh 191
#define Zz 13
#define Vv 8185
#define G4 764      // 4*H
#define NP 768      // padded 4H (gate-interleaved)
#define VP 8192     // padded V
#define START_TOK 19

// -------- persistent device scratch (no allocations allowed) --------
__device__ float g_h[2][Bz * Hh];
__device__ float g_c[Bz * Hh];
__device__ unsigned long long g_amax[2][Bz];
__device__ float g_encx[Bz * Tt * G4];   // encoder input projections (+bias), PG layout
__device__ float g_decp[Vv * G4];        // vocab decoder projections (+bias), PG layout
__device__ float g_wk1[Ee * NP];         // inf_k, PG, padded
__device__ float g_wk2[Ee * NP];         // gen_k, PG, padded
__device__ float g_wr1[Hh * NP];         // inf_rk, PG, padded
__device__ float g_wr2[Hh * NP];         // gen_rk, PG, padded
__device__ float g_wlog[Hh * VP];        // out_w, padded to 8192 cols
__device__ unsigned g_bar1;              // encoder barrier counter
__device__ unsigned g_bar2;              // decoder barrier counter

// -------- helpers --------
__device__ __forceinline__ float sigf(float x) { return 1.f / (1.f + expf(-x)); }

__device__ __forceinline__ void ffma2(unsigned long long& d, unsigned long long a,
                                      unsigned long long b) {
    asm("fma.rn.f32x2 %0, %1, %2, %3;" : "=l"(d) : "l"(a), "l"(b), "l"(d));
}
__device__ __forceinline__ unsigned long long dup2(float x) {
    unsigned long long r;
    asm("mov.b64 %0, {%1, %1};" : "=l"(r) : "f"(x));
    return r;
}
__device__ __forceinline__ float2 unpk(unsigned long long v) {
    float2 r;
    asm("mov.b64 {%0, %1}, %2;" : "=f"(r.x), "=f"(r.y) : "l"(v));
    return r;
}

// Grid-wide barrier: monotonic counter, release-arrive / acquire-spin.
__device__ __forceinline__ void grid_bar(unsigned* ctr, unsigned target) {
    __syncthreads();
    if (threadIdx.x == 0) {
        __threadfence();
        atomicAdd(ctr, 1u);
        unsigned v;
        do {
            asm volatile("ld.acquire.gpu.u32 %0, [%1];" : "=r"(v) : "l"(ctr));
        } while (v < target);
    }
    __syncthreads();
}

// -------- shared memory layouts --------
struct SmemLstm { float hs[8][Hh + 1]; float ws[24][260]; };
struct SmemLog  { float hs[32][Hh + 1]; };
union SmemU { SmemLstm l; SmemLog g; };

// -------- setup: zero state + barrier counters + all weight permutes --------
#define N_A (Bz * Hh)
#define N_K (Ee * NP)
#define N_R (Hh * NP)
#define N_V (Hh * VP)
#define N_SETUP (N_A + 2 * N_K + 2 * N_R + N_V)

__global__ void setup_kernel(const float* __restrict__ inf_k, const float* __restrict__ gen_k,
                             const float* __restrict__ inf_rk, const float* __restrict__ gen_rk,
                             const float* __restrict__ out_w)
{
    int i = blockIdx.x * 256 + threadIdx.x;
    if (i == 0) { g_bar1 = 0u; g_bar2 = 0u; }
    if (i < N_A) { g_h[0][i] = 0.f; g_c[i] = 0.f; return; }
    i -= N_A;
    if (i < N_K) {
        int k = i / NP, n = i - k * NP;
        g_wk1[i] = (n < G4) ? inf_k[k * G4 + (n & 3) * Hh + (n >> 2)] : 0.f;
        return;
    }
    i -= N_K;
    if (i < N_K) {
        int k = i / NP, n = i - k * NP;
        g_wk2[i] = (n < G4) ? gen_k[k * G4 + (n & 3) * Hh + (n >> 2)] : 0.f;
        return;
    }
    i -= N_K;
    if (i < N_R) {
        int k = i / NP, n = i - k * NP;
        g_wr1[i] = (n < G4) ? inf_rk[k * G4 + (n & 3) * Hh + (n >> 2)] : 0.f;
        return;
    }
    i -= N_R;
    if (i < N_R) {
        int k = i / NP, n = i - k * NP;
        g_wr2[i] = (n < G4) ? gen_rk[k * G4 + (n & 3) * Hh + (n >> 2)] : 0.f;
        return;
    }
    i -= N_R;
    if (i < N_V) {
        int k = i >> 13, v = i & (VP - 1);
        g_wlog[i] = (v < Vv) ? out_w[k * Vv + v] : 0.f;
    }
}

// -------- input projection GEMM (gathered rows) --------
__global__ __launch_bounds__(256) void proj_kernel(
    const int* __restrict__ idx, int M,
    const float* __restrict__ emb,
    const float* __restrict__ Wpg,    // [Ee][NP]
    const float* __restrict__ bias,   // [G4] original gate-block order
    float* __restrict__ outp)         // [M][G4]
{
    __shared__ float A[32][Ee + 3];
    int tid = threadIdx.x, cc = tid & 31, rr = tid >> 5;
    int c0 = blockIdx.x * 256, r0 = blockIdx.y * 32;

    for (int i = tid; i < 32 * Ee; i += 256) {
        int r = i / Ee, k = i - r * Ee;
        int m = r0 + r;
        int tok = (m < M) ? (idx ? idx[m] : m) : 0;
        A[r][k] = emb[tok * Ee + k];
    }
    __syncthreads();

    int ca = c0 + cc * 4, cb = ca + 128;
    unsigned long long acc[4][4];
#pragma unroll
    for (int r = 0; r < 4; r++)
#pragma unroll
        for (int q = 0; q < 4; q++) acc[r][q] = 0ull;

    const ulonglong2* wa = (const ulonglong2*)(Wpg + ca);
    const ulonglong2* wb = (const ulonglong2*)(Wpg + cb);
#pragma unroll 2
    for (int k = 0; k < Ee; k++) {
        ulonglong2 w0 = wa[k * (NP / 4)];
        ulonglong2 w1 = wb[k * (NP / 4)];
#pragma unroll
        for (int r = 0; r < 4; r++) {
            unsigned long long hp = dup2(A[rr + 8 * r][k]);
            ffma2(acc[r][0], hp, w0.x);
            ffma2(acc[r][1], hp, w0.y);
            ffma2(acc[r][2], hp, w1.x);
            ffma2(acc[r][3], hp, w1.y);
        }
    }

    int ja = ca >> 2, jb = cb >> 2;
    bool cbok = (jb < Hh);
    float ba[4], bb[4];
#pragma unroll
    for (int g = 0; g < 4; g++) {
        ba[g] = bias[g * Hh + ja];
        bb[g] = cbok ? bias[g * Hh + jb] : 0.f;
    }
#pragma unroll
    for (int r = 0; r < 4; r++) {
        int m = r0 + rr + 8 * r;
        if (m >= M) continue;
        float* op = outp + (size_t)m * G4;
        float2 v01 = unpk(acc[r][0]), v23 = unpk(acc[r][1]);
        float2 v45 = unpk(acc[r][2]), v67 = unpk(acc[r][3]);
        float4 va = make_float4(v01.x + ba[0], v01.y + ba[1], v23.x + ba[2], v23.y + ba[3]);
        *(float4*)(op + ca) = va;
        if (cbok) {
            float4 vb = make_float4(v45.x + bb[0], v45.y + bb[1], v67.x + bb[2], v67.y + bb[3]);
            *(float4*)(op + cb) = vb;
        }
    }
}

// -------- LSTM step phase (device fn; blk in [0,96)) --------
// block = 64 unit-threads x 4 rowthreads; thread: 1 unit, 2 rows.
__device__ __forceinline__ void lstm_phase(
    SmemLstm& sm, int blk,
    const float* __restrict__ Wpg,      // [Hh][NP]
    const float* __restrict__ h_prev,
    float* __restrict__ h_new,
    const float* __restrict__ pre_base,
    int t, int mode,
    const unsigned long long* __restrict__ amax_in,
    unsigned long long* __restrict__ amax_out)
{
    int tid = threadIdx.x;
    int u = tid & 63, rt = tid >> 6;
    int u0 = (blk % 3) * 64, r0 = (blk / 3) * 8;
    int j = u0 + u;
    int row1 = r0 + rt, row2 = row1 + 4;

    if (mode && blk == 0) amax_out[tid] = 0ull;   // reset this step's argmax buffer

    for (int i = tid; i < 8 * Hh; i += 256) {
        int r = i / Hh, k = i - r * Hh;
        sm.hs[r][k] = h_prev[(r0 + r) * Hh + k];
    }

    float4 p1 = make_float4(0.f, 0.f, 0.f, 0.f), p2 = p1;
    if (j < Hh) {
        const float *pb1, *pb2;
        if (mode == 0) {
            pb1 = pre_base + ((size_t)row1 * Tt + t) * G4;
            pb2 = pre_base + ((size_t)row2 * Tt + t) * G4;
        } else if (mode == 1) {
            pb1 = pb2 = pre_base + (size_t)START_TOK * G4;
        } else {
            int t1 = Vv - 1 - (int)(unsigned)(amax_in[row1] & 0xFFFFFFFFull);
            int t2 = Vv - 1 - (int)(unsigned)(amax_in[row2] & 0xFFFFFFFFull);
            pb1 = pre_base + (size_t)t1 * G4;
            pb2 = pre_base + (size_t)t2 * G4;
        }
        p1 = *(const float4*)(pb1 + 4 * j);
        p2 = *(const float4*)(pb2 + 4 * j);
    }
    __syncthreads();

    unsigned long long a1[2] = {0ull, 0ull}, a2[2] = {0ull, 0ull};
    for (int kc = 0; kc < Hh; kc += 24) {
        int kn = min(24, Hh - kc);
        for (int i = tid; i < kn * 64; i += 256) {
            int kk = i >> 6, uu = i & 63;
            *(float4*)&sm.ws[kk][uu * 4] = *(const float4*)(Wpg + (kc + kk) * NP + (u0 + uu) * 4);
        }
        __syncthreads();
        for (int kk = 0; kk < kn; kk++) {
            ulonglong2 w = *(const ulonglong2*)&sm.ws[kk][u * 4];
            unsigned long long h1 = dup2(sm.hs[rt][kc + kk]);
            unsigned long long h2 = dup2(sm.hs[rt + 4][kc + kk]);
            ffma2(a1[0], h1, w.x); ffma2(a1[1], h1, w.y);
            ffma2(a2[0], h2, w.x); ffma2(a2[1], h2, w.y);
        }
        __syncthreads();
    }

    if (j < Hh) {
        float2 g01 = unpk(a1[0]), g23 = unpk(a1[1]);
        {
            float iv = sigf(g01.x + p1.x);
            float fv = sigf(g01.y + p1.y);
            float gv = tanhf(g23.x + p1.z);
            float ov = sigf(g23.y + p1.w);
            float cp = g_c[row1 * Hh + j];
            float cn = fv * cp + iv * gv;
            g_c[row1 * Hh + j] = cn;
            h_new[row1 * Hh + j] = ov * tanhf(cn);
        }
        g01 = unpk(a2[0]); g23 = unpk(a2[1]);
        {
            float iv = sigf(g01.x + p2.x);
            float fv = sigf(g01.y + p2.y);
            float gv = tanhf(g23.x + p2.z);
            float ov = sigf(g23.y + p2.w);
            float cp = g_c[row2 * Hh + j];
            float cn = fv * cp + iv * gv;
            g_c[row2 * Hh + j] = cn;
            h_new[row2 * Hh + j] = ov * tanhf(cn);
        }
    }
}

// -------- logits GEMM + fused argmax phase (device fn; blk in [0,256)) --------
__device__ __forceinline__ void logits_phase(
    SmemLog& sm, int blk,
    const float* __restrict__ hsrc,
    const float* __restrict__ Wlog,   // [Hh][VP]
    const float* __restrict__ bo,
    float* __restrict__ out, int t,
    unsigned long long* __restrict__ amax)
{
    int tid = threadIdx.x, cc = tid & 31, rr = tid >> 5;
    int c0 = (blk & 31) * 256, r0 = (blk >> 5) * 32;

    for (int i = tid; i < 32 * Hh; i += 256) {
        int r = i / Hh, k = i - r * Hh;
        sm.hs[r][k] = hsrc[(r0 + r) * Hh + k];
    }
    __syncthreads();

    int ca = c0 + cc * 4, cb = ca + 128;
    unsigned long long acc[4][4];
#pragma unroll
    for (int r = 0; r < 4; r++)
#pragma unroll
        for (int q = 0; q < 4; q++) acc[r][q] = 0ull;

    const ulonglong2* wa = (const ulonglong2*)(Wlog + ca);
    const ulonglong2* wb = (const ulonglong2*)(Wlog + cb);
#pragma unroll 2
    for (int k = 0; k < Hh; k++) {
        ulonglong2 w0 = wa[k * (VP / 4)];
        ulonglong2 w1 = wb[k * (VP / 4)];
#pragma unroll
        for (int r = 0; r < 4; r++) {
            unsigned long long hp = dup2(sm.hs[rr + 8 * r][k]);
            ffma2(acc[r][0], hp, w0.x);
            ffma2(acc[r][1], hp, w0.y);
            ffma2(acc[r][2], hp, w1.x);
            ffma2(acc[r][3], hp, w1.y);
        }
    }

    float ba0 = bo[ca], ba1 = bo[ca + 1], ba2 = bo[ca + 2], ba3 = bo[ca + 3];
    float bb0 = (cb < Vv) ? bo[cb] : 0.f;
    float bb1 = (cb + 1 < Vv) ? bo[cb + 1] : 0.f;
    float bb2 = (cb + 2 < Vv) ? bo[cb + 2] : 0.f;
    float bb3 = (cb + 3 < Vv) ? bo[cb + 3] : 0.f;

#pragma unroll
    for (int r = 0; r < 4; r++) {
        int row = r0 + rr + 8 * r;
        float* orow = out + ((size_t)row * Tt + t) * Vv;
        float2 v01 = unpk(acc[r][0]), v23 = unpk(acc[r][1]);
        float2 v45 = unpk(acc[r][2]), v67 = unpk(acc[r][3]);
        float v[8];
        v[0] = v01.x + ba0; v[1] = v01.y + ba1; v[2] = v23.x + ba2; v[3] = v23.y + ba3;
        v[4] = v45.x + bb0; v[5] = v45.y + bb1; v[6] = v67.x + bb2; v[7] = v67.y + bb3;

        orow[ca] = v[0]; orow[ca + 1] = v[1]; orow[ca + 2] = v[2]; orow[ca + 3] = v[3];
        if (cb < Vv)     orow[cb]     = v[4];
        if (cb + 1 < Vv) orow[cb + 1] = v[5];
        if (cb + 2 < Vv) orow[cb + 2] = v[6];
        if (cb + 3 < Vv) orow[cb + 3] = v[7];

        unsigned long long key = 0ull;
#pragma unroll
        for (int g = 0; g < 8; g++) {
            int col = (g < 4) ? ca + g : cb + g - 4;
            unsigned long long kk2 = 0ull;
            if (col < Vv) {
                unsigned u_ = __float_as_uint(v[g]);
                unsigned m = (u_ & 0x80000000u) ? ~u_ : (u_ | 0x80000000u);
                kk2 = ((unsigned long long)m << 32) | (unsigned)(Vv - 1 - col);
            }
            key = (kk2 > key) ? kk2 : key;
        }
#pragma unroll
        for (int s = 16; s > 0; s >>= 1) {
            unsigned long long o = __shfl_xor_sync(0xFFFFFFFFu, key, s);
            key = (o > key) ? o : key;
        }
        if (cc == 0) atomicMax(&amax[row], key);
    }
    __syncthreads();   // protect sm.hs before next phase reuses the union
}

// -------- persistent encoder: 25 steps, 96 blocks --------
__global__ __launch_bounds__(256) void enc_kernel()
{
    __shared__ SmemLstm sm;
    int blk = blockIdx.x;
    unsigned n = 0;
    for (int t = 0; t < Tt; t++) {
        lstm_phase(sm, blk, g_wr1, g_h[t & 1], g_h[(t & 1) ^ 1], g_encx, t, 0,
                   nullptr, nullptr);
        if (t < Tt - 1) { n++; grid_bar(&g_bar1, n * 96u); }
    }
}

// -------- latent head --------
__global__ void latent_kernel(const float* __restrict__ eps,
                              const float* __restrict__ mu_w, const float* __restrict__ mu_b,
                              const float* __restrict__ sig_w, const float* __restrict__ sig_b,
                              const float* __restrict__ init_w, const float* __restrict__ init_b)
{
    __shared__ float hrow[Hh];
    __shared__ float z_s[Zz];
    int b = blockIdx.x, tid = threadIdx.x;
    if (tid < Hh) hrow[tid] = g_h[1][b * Hh + tid];    // encoder final h (25 odd steps)
    __syncthreads();
    if (tid < Zz) {
        float mu = mu_b[tid], sg = sig_b[tid];
        for (int k = 0; k < Hh; k++) {
            mu = fmaf(hrow[k], mu_w[k * Zz + tid], mu);
            sg = fmaf(hrow[k], sig_w[k * Zz + tid], sg);
        }
        z_s[tid] = mu + eps[tid] * sg;
    }
    __syncthreads();
    if (tid < Hh) {
        float v = init_b[tid];
#pragma unroll
        for (int z = 0; z < Zz; z++) v = fmaf(z_s[z], init_w[z * Hh + tid], v);
        g_h[0][b * Hh + tid] = v;
        g_c[b * Hh + tid] = v;
    }
}

// -------- persistent decoder: 25x (lstm -> barrier -> logits+argmax -> barrier) --------
__global__ __launch_bounds__(256, 2) void dec_kernel(const float* __restrict__ bo,
                                                     float* __restrict__ out)
{
    __shared__ SmemU sm;
    int blk = blockIdx.x;
    unsigned n = 0;
    for (int t = 0; t < Tt; t++) {
        int p = t & 1;
        if (blk < 96) {
            lstm_phase(sm.l, blk, g_wr2, g_h[p], g_h[p ^ 1], g_decp, t,
                       (t == 0) ? 1 : 2, g_amax[p ^ 1], g_amax[p]);
        }
        n++; grid_bar(&g_bar2, n * 256u);
        logits_phase(sm.g, blk, g_h[p ^ 1], g_wlog, bo, out, t, g_amax[p]);
        if (t < Tt - 1) { n++; grid_bar(&g_bar2, n * 256u); }
    }
}

// -------- host orchestration (exactly 6 graph nodes) --------
extern "C" void kernel_launch(void* const* d_in, const int* in_sizes, int n_in,
                              void* d_out, int out_size)
{
    const int*   inputs = (const int*)  d_in[0];
    const float* eps    = (const float*)d_in[1];
    const float* emb    = (const float*)d_in[2];
    const float* inf_k  = (const float*)d_in[3];
    const float* inf_rk = (const float*)d_in[4];
    const float* inf_b  = (const float*)d_in[5];
    const float* mu_w   = (const float*)d_in[6];
    const float* mu_b   = (const float*)d_in[7];
    const float* sig_w  = (const float*)d_in[8];
    const float* sig_b  = (const float*)d_in[9];
    const float* init_w = (const float*)d_in[10];
    const float* init_b = (const float*)d_in[11];
    const float* gen_k  = (const float*)d_in[12];
    const float* gen_rk = (const float*)d_in[13];
    const float* gen_b  = (const float*)d_in[14];
    const float* out_w  = (const float*)d_in[15];
    const float* out_b  = (const float*)d_in[16];
    float* out = (float*)d_out;

    float *encx, *decp, *wk1, *wk2;
    cudaGetSymbolAddress((void**)&encx, g_encx);
    cudaGetSymbolAddress((void**)&decp, g_decp);
    cudaGetSymbolAddress((void**)&wk1,  g_wk1);
    cudaGetSymbolAddress((void**)&wk2,  g_wk2);

    setup_kernel<<<(N_SETUP + 255) / 256, 256>>>(inf_k, gen_k, inf_rk, gen_rk, out_w);
    proj_kernel<<<dim3(3, (Bz * Tt + 31) / 32), 256>>>(inputs, Bz * Tt, emb, wk1, inf_b, encx);
    proj_kernel<<<dim3(3, (Vv + 31) / 32), 256>>>(nullptr, Vv, emb, wk2, gen_b, decp);
    enc_kernel<<<96, 256>>>();
    latent_kernel<<<Bz, 192>>>(eps, mu_w, mu_b, sig_w, sig_b, init_w, init_b);
    dec_kernel<<<256, 256>>>(out_b, out);
}

// round 8
// speedup vs baseline: 1.2449x; 1.2449x over previous
#include <cuda_runtime.h>
#include <math.h>
#include <stdint.h>

#define Bz 256
#define Tt 25
#define Ee 353
#define Hh 191
#define Zz 13
#define Vv 8185
#define G4 764      // 4*H
#define NP 768      // padded 4H (gate-interleaved)
#define VP 8192     // padded V
#define START_TOK 19

// -------- persistent device scratch (no allocations allowed) --------
__device__ float g_h[2][Bz * Hh];
__device__ float g_c[Bz * Hh];
__device__ unsigned long long g_amax[2][Bz];
__device__ float g_encx[Bz * Tt * G4];   // encoder input projections (+bias), PG layout
__device__ float g_decp[Vv * G4];        // vocab decoder projections (+bias), PG layout
__device__ float g_wk1[Ee * NP];         // inf_k, PG, padded
__device__ float g_wk2[Ee * NP];         // gen_k, PG, padded
__device__ float g_wr1[Hh * NP];         // inf_rk, PG, padded
__device__ float g_wr2[Hh * NP];         // gen_rk, PG, padded
__device__ float g_wlog[Hh * VP];        // out_w, padded to 8192 cols

// -------- helpers --------
__device__ __forceinline__ float sigf(float x) { return 1.f / (1.f + expf(-x)); }

__device__ __forceinline__ void ffma2(unsigned long long& d, unsigned long long a,
                                      unsigned long long b) {
    asm("fma.rn.f32x2 %0, %1, %2, %3;" : "=l"(d) : "l"(a), "l"(b), "l"(d));
}
__device__ __forceinline__ unsigned long long dup2(float x) {
    unsigned long long r;
    asm("mov.b64 %0, {%1, %1};" : "=l"(r) : "f"(x));
    return r;
}
__device__ __forceinline__ float2 unpk(unsigned long long v) {
    float2 r;
    asm("mov.b64 {%0, %1}, %2;" : "=f"(r.x), "=f"(r.y) : "l"(v));
    return r;
}

// -------- setup: zero state + all weight permutes (one kernel) --------
#define N_A (Bz * Hh)
#define N_K (Ee * NP)
#define N_R (Hh * NP)
#define N_V (Hh * VP)
#define N_SETUP (N_A + 2 * N_K + 2 * N_R + N_V)

__global__ void setup_kernel(const float* __restrict__ inf_k, const float* __restrict__ gen_k,
                             const float* __restrict__ inf_rk, const float* __restrict__ gen_rk,
                             const float* __restrict__ out_w)
{
    int i = blockIdx.x * 256 + threadIdx.x;
    if (i < N_A) { g_h[0][i] = 0.f; g_c[i] = 0.f; return; }
    i -= N_A;
    if (i < N_K) {
        int k = i / NP, n = i - k * NP;
        g_wk1[i] = (n < G4) ? inf_k[k * G4 + (n & 3) * Hh + (n >> 2)] : 0.f;
        return;
    }
    i -= N_K;
    if (i < N_K) {
        int k = i / NP, n = i - k * NP;
        g_wk2[i] = (n < G4) ? gen_k[k * G4 + (n & 3) * Hh + (n >> 2)] : 0.f;
        return;
    }
    i -= N_K;
    if (i < N_R) {
        int k = i / NP, n = i - k * NP;
        g_wr1[i] = (n < G4) ? inf_rk[k * G4 + (n & 3) * Hh + (n >> 2)] : 0.f;
        return;
    }
    i -= N_R;
    if (i < N_R) {
        int k = i / NP, n = i - k * NP;
        g_wr2[i] = (n < G4) ? gen_rk[k * G4 + (n & 3) * Hh + (n >> 2)] : 0.f;
        return;
    }
    i -= N_R;
    if (i < N_V) {
        int k = i >> 13, v = i & (VP - 1);
        g_wlog[i] = (v < Vv) ? out_w[k * Vv + v] : 0.f;
    }
}

// -------- input projection GEMM (gathered rows), FFMA2 (R2-validated + unroll 4) ----
__global__ __launch_bounds__(256) void proj_kernel(
    const int* __restrict__ idx, int M,
    const float* __restrict__ emb,
    const float* __restrict__ Wpg,    // [Ee][NP]
    const float* __restrict__ bias,   // [G4] original gate-block order
    float* __restrict__ outp)         // [M][G4]
{
    __shared__ float A[32][Ee + 3];
    int tid = threadIdx.x, cc = tid & 31, rr = tid >> 5;
    int c0 = blockIdx.x * 256, r0 = blockIdx.y * 32;

    for (int i = tid; i < 32 * Ee; i += 256) {
        int r = i / Ee, k = i - r * Ee;
        int m = r0 + r;
        int tok = (m < M) ? (idx ? idx[m] : m) : 0;
        A[r][k] = emb[tok * Ee + k];
    }
    __syncthreads();

    int ca = c0 + cc * 4, cb = ca + 128;
    unsigned long long acc[4][4];
#pragma unroll
    for (int r = 0; r < 4; r++)
#pragma unroll
        for (int q = 0; q < 4; q++) acc[r][q] = 0ull;

    const ulonglong2* wa = (const ulonglong2*)(Wpg + ca);
    const ulonglong2* wb = (const ulonglong2*)(Wpg + cb);
#pragma unroll 4
    for (int k = 0; k < Ee; k++) {
        ulonglong2 w0 = wa[k * (NP / 4)];
        ulonglong2 w1 = wb[k * (NP / 4)];
#pragma unroll
        for (int r = 0; r < 4; r++) {
            unsigned long long hp = dup2(A[rr + 8 * r][k]);
            ffma2(acc[r][0], hp, w0.x);
            ffma2(acc[r][1], hp, w0.y);
            ffma2(acc[r][2], hp, w1.x);
            ffma2(acc[r][3], hp, w1.y);
        }
    }

    int ja = ca >> 2, jb = cb >> 2;
    bool cbok = (jb < Hh);
    float ba[4], bb[4];
#pragma unroll
    for (int g = 0; g < 4; g++) {
        ba[g] = bias[g * Hh + ja];
        bb[g] = cbok ? bias[g * Hh + jb] : 0.f;
    }
#pragma unroll
    for (int r = 0; r < 4; r++) {
        int m = r0 + rr + 8 * r;
        if (m >= M) continue;
        float* op = outp + (size_t)m * G4;
        float2 v01 = unpk(acc[r][0]), v23 = unpk(acc[r][1]);
        float2 v45 = unpk(acc[r][2]), v67 = unpk(acc[r][3]);
        float4 va = make_float4(v01.x + ba[0], v01.y + ba[1], v23.x + ba[2], v23.y + ba[3]);
        *(float4*)(op + ca) = va;
        if (cbok) {
            float4 vb = make_float4(v45.x + bb[0], v45.y + bb[1], v67.x + bb[2], v67.y + bb[3]);
            *(float4*)(op + cb) = vb;
        }
    }
}

// -------- LSTM recurrent step v2 --------
// 256 threads = 32 units x 8 row-threads, 1 row each. grid (6, 32).
// W read directly from L2 (no smem staging, single __syncthreads).
__global__ __launch_bounds__(256) void lstm_step(
    const float* __restrict__ Wpg,      // [Hh][NP]
    const float* __restrict__ h_prev,
    float* __restrict__ h_new,
    const float* __restrict__ pre_base,
    int t, int mode,
    const unsigned long long* __restrict__ amax_in,
    unsigned long long* __restrict__ amax_out)
{
    __shared__ unsigned long long hs[8][192];   // h duplicated as f32x2
    int tid = threadIdx.x;
    int u = tid & 31, rt = tid >> 5;            // unit-in-tile, row-in-tile
    int u0 = blockIdx.x * 32, r0 = blockIdx.y * 8;
    int j = u0 + u;                             // unit in [0,192)
    int row = r0 + rt;

    if (mode && u == 0 && blockIdx.x == 0) amax_out[row] = 0ull;

    for (int i = tid; i < 8 * 192; i += 256) {
        int r = i / 192, k = i - r * 192;
        float v = (k < Hh) ? h_prev[(r0 + r) * Hh + k] : 0.f;
        hs[r][k] = dup2(v);
    }

    float4 p = make_float4(0.f, 0.f, 0.f, 0.f);
    if (j < Hh) {
        const float* pb;
        if (mode == 0) {
            pb = pre_base + ((size_t)row * Tt + t) * G4;
        } else if (mode == 1) {
            pb = pre_base + (size_t)START_TOK * G4;
        } else {
            int tok = Vv - 1 - (int)(unsigned)(amax_in[row] & 0xFFFFFFFFull);
            pb = pre_base + (size_t)tok * G4;
        }
        p = *(const float4*)(pb + 4 * j);
    }
    __syncthreads();

    unsigned long long a0 = 0ull, a1 = 0ull;
    const ulonglong2* wp = (const ulonglong2*)(Wpg + j * 4);
#pragma unroll 8
    for (int k = 0; k < Hh; k++) {
        ulonglong2 w = wp[k * (NP / 4)];
        unsigned long long hv = hs[rt][k];
        ffma2(a0, hv, w.x);
        ffma2(a1, hv, w.y);
    }

    if (j < Hh) {
        float2 g01 = unpk(a0), g23 = unpk(a1);
        float iv = sigf(g01.x + p.x);
        float fv = sigf(g01.y + p.y);
        float gv = tanhf(g23.x + p.z);
        float ov = sigf(g23.y + p.w);
        float cp = g_c[row * Hh + j];
        float cn = fv * cp + iv * gv;
        g_c[row * Hh + j] = cn;
        h_new[row * Hh + j] = ov * tanhf(cn);
    }
}

// -------- latent head --------
__global__ void latent_kernel(const float* __restrict__ h_enc, const float* __restrict__ eps,
                              const float* __restrict__ mu_w, const float* __restrict__ mu_b,
                              const float* __restrict__ sig_w, const float* __restrict__ sig_b,
                              const float* __restrict__ init_w, const float* __restrict__ init_b,
                              float* __restrict__ h_dec)
{
    __shared__ float hrow[Hh];
    __shared__ float z_s[Zz];
    int b = blockIdx.x, tid = threadIdx.x;
    if (tid < Hh) hrow[tid] = h_enc[b * Hh + tid];
    __syncthreads();
    if (tid < Zz) {
        float mu = mu_b[tid], sg = sig_b[tid];
        for (int k = 0; k < Hh; k++) {
            mu = fmaf(hrow[k], mu_w[k * Zz + tid], mu);
            sg = fmaf(hrow[k], sig_w[k * Zz + tid], sg);
        }
        z_s[tid] = mu + eps[tid] * sg;
    }
    __syncthreads();
    if (tid < Hh) {
        float v = init_b[tid];
#pragma unroll
        for (int z = 0; z < Zz; z++) v = fmaf(z_s[z], init_w[z * Hh + tid], v);
        h_dec[b * Hh + tid] = v;
        g_c[b * Hh + tid] = v;
    }
}

// -------- logits GEMM + fused argmax v2 --------
// tile 16 rows x 256 cols; 256 threads = 32 col-threads x 8 row-threads, 2 rows each.
// grid (32, 16) = 512 CTAs. h pre-duplicated as f32x2 in smem.
__global__ __launch_bounds__(256) void logits_kernel(
    const float* __restrict__ hsrc,
    const float* __restrict__ W,      // [Hh][VP]
    const float* __restrict__ bo,
    float* __restrict__ out, int t,
    unsigned long long* __restrict__ amax)
{
    __shared__ unsigned long long hs[16][192];
    int tid = threadIdx.x, cc = tid & 31, rr = tid >> 5;
    int c0 = blockIdx.x * 256, r0 = blockIdx.y * 16;

    for (int i = tid; i < 16 * 192; i += 256) {
        int r = i / 192, k = i - r * 192;
        float v = (k < Hh) ? hsrc[(r0 + r) * Hh + k] : 0.f;
        hs[r][k] = dup2(v);
    }
    __syncthreads();

    int ca = c0 + cc * 4, cb = ca + 128;
    unsigned long long acc[2][4];
#pragma unroll
    for (int r = 0; r < 2; r++)
#pragma unroll
        for (int q = 0; q < 4; q++) acc[r][q] = 0ull;

    const ulonglong2* wa = (const ulonglong2*)(W + ca);
    const ulonglong2* wb = (const ulonglong2*)(W + cb);
#pragma unroll 4
    for (int k = 0; k < Hh; k++) {
        ulonglong2 w0 = wa[k * (VP / 4)];
        ulonglong2 w1 = wb[k * (VP / 4)];
        unsigned long long h0 = hs[rr][k];
        unsigned long long h1 = hs[rr + 8][k];
        ffma2(acc[0][0], h0, w0.x);
        ffma2(acc[0][1], h0, w0.y);
        ffma2(acc[0][2], h0, w1.x);
        ffma2(acc[0][3], h0, w1.y);
        ffma2(acc[1][0], h1, w0.x);
        ffma2(acc[1][1], h1, w0.y);
        ffma2(acc[1][2], h1, w1.x);
        ffma2(acc[1][3], h1, w1.y);
    }

    float ba0 = bo[ca], ba1 = bo[ca + 1], ba2 = bo[ca + 2], ba3 = bo[ca + 3];
    float bb0 = (cb < Vv) ? bo[cb] : 0.f;
    float bb1 = (cb + 1 < Vv) ? bo[cb + 1] : 0.f;
    float bb2 = (cb + 2 < Vv) ? bo[cb + 2] : 0.f;
    float bb3 = (cb + 3 < Vv) ? bo[cb + 3] : 0.f;

#pragma unroll
    for (int r = 0; r < 2; r++) {
        int row = r0 + rr + 8 * r;
        float* orow = out + ((size_t)row * Tt + t) * Vv;
        float2 v01 = unpk(acc[r][0]), v23 = unpk(acc[r][1]);
        float2 v45 = unpk(acc[r][2]), v67 = unpk(acc[r][3]);
        float v[8];
        v[0] = v01.x + ba0; v[1] = v01.y + ba1; v[2] = v23.x + ba2; v[3] = v23.y + ba3;
        v[4] = v45.x + bb0; v[5] = v45.y + bb1; v[6] = v67.x + bb2; v[7] = v67.y + bb3;

        orow[ca] = v[0]; orow[ca + 1] = v[1]; orow[ca + 2] = v[2]; orow[ca + 3] = v[3];
        if (cb < Vv)     orow[cb]     = v[4];
        if (cb + 1 < Vv) orow[cb + 1] = v[5];
        if (cb + 2 < Vv) orow[cb + 2] = v[6];
        if (cb + 3 < Vv) orow[cb + 3] = v[7];

        unsigned long long key = 0ull;
#pragma unroll
        for (int g = 0; g < 8; g++) {
            int col = (g < 4) ? ca + g : cb + g - 4;
            unsigned long long kk2 = 0ull;
            if (col < Vv) {
                unsigned u_ = __float_as_uint(v[g]);
                unsigned m = (u_ & 0x80000000u) ? ~u_ : (u_ | 0x80000000u);
                kk2 = ((unsigned long long)m << 32) | (unsigned)(Vv - 1 - col);
            }
            key = (kk2 > key) ? kk2 : key;
        }
#pragma unroll
        for (int s = 16; s > 0; s >>= 1) {
            unsigned long long o = __shfl_xor_sync(0xFFFFFFFFu, key, s);
            key = (o > key) ? o : key;
        }
        if (cc == 0) atomicMax(&amax[row], key);
    }
}

// -------- host orchestration --------
extern "C" void kernel_launch(void* const* d_in, const int* in_sizes, int n_in,
                              void* d_out, int out_size)
{
    const int*   inputs = (const int*)  d_in[0];
    const float* eps    = (const float*)d_in[1];
    const float* emb    = (const float*)d_in[2];
    const float* inf_k  = (const float*)d_in[3];
    const float* inf_rk = (const float*)d_in[4];
    const float* inf_b  = (const float*)d_in[5];
    const float* mu_w   = (const float*)d_in[6];
    const float* mu_b   = (const float*)d_in[7];
    const float* sig_w  = (const float*)d_in[8];
    const float* sig_b  = (const float*)d_in[9];
    const float* init_w = (const float*)d_in[10];
    const float* init_b = (const float*)d_in[11];
    const float* gen_k  = (const float*)d_in[12];
    const float* gen_rk = (const float*)d_in[13];
    const float* gen_b  = (const float*)d_in[14];
    const float* out_w  = (const float*)d_in[15];
    const float* out_b  = (const float*)d_in[16];
    float* out = (float*)d_out;

    float *hbase, *encx, *decp, *wk1, *wk2, *wr1, *wr2, *wlog;
    unsigned long long* ambase;
    cudaGetSymbolAddress((void**)&hbase,  g_h);
    cudaGetSymbolAddress((void**)&encx,   g_encx);
    cudaGetSymbolAddress((void**)&decp,   g_decp);
    cudaGetSymbolAddress((void**)&wk1,    g_wk1);
    cudaGetSymbolAddress((void**)&wk2,    g_wk2);
    cudaGetSymbolAddress((void**)&wr1,    g_wr1);
    cudaGetSymbolAddress((void**)&wr2,    g_wr2);
    cudaGetSymbolAddress((void**)&wlog,   g_wlog);
    cudaGetSymbolAddress((void**)&ambase, g_amax);

    float* hbuf[2] = {hbase, hbase + Bz * Hh};
    unsigned long long* am[2] = {ambase, ambase + Bz};

    setup_kernel<<<(N_SETUP + 255) / 256, 256>>>(inf_k, gen_k, inf_rk, gen_rk, out_w);
    proj_kernel<<<dim3(3, (Bz * Tt + 31) / 32), 256>>>(inputs, Bz * Tt, emb, wk1, inf_b, encx);
    proj_kernel<<<dim3(3, (Vv + 31) / 32), 256>>>(nullptr, Vv, emb, wk2, gen_b, decp);

    dim3 lgrid(6, 32);    // 6 unit tiles (192) x 32 row tiles (256)
    dim3 ogrid(32, 16);   // 32 v tiles (8192) x 16 row tiles (256)

    // ----- encoder -----
    int cur = 0;
    for (int t = 0; t < Tt; t++) {
        lstm_step<<<lgrid, 256>>>(wr1, hbuf[cur], hbuf[cur ^ 1], encx, t, 0,
                                  nullptr, nullptr);
        cur ^= 1;
    }

    // ----- latent -----
    latent_kernel<<<Bz, 192>>>(hbuf[cur], eps, mu_w, mu_b, sig_w, sig_b,
                               init_w, init_b, hbuf[cur ^ 1]);
    cur ^= 1;

    // ----- autoregressive decoder -----
    for (int t = 0; t < Tt; t++) {
        int p = t & 1;
        lstm_step<<<lgrid, 256>>>(wr2, hbuf[cur], hbuf[cur ^ 1], decp, t,
                                  (t == 0) ? 1 : 2, am[p ^ 1], am[p]);
        cur ^= 1;
        logits_kernel<<<ogrid, 256>>>(hbuf[cur], wlog, out_b, out, t, am[p]);
    }
}

// round 13
// speedup vs baseline: 1.9259x; 1.5470x over previous
#include <cuda_runtime.h>
#include <math.h>
#include <stdint.h>

#define Bz 256
#define Tt 25
#define Ee 353
#define Hh 191
#define Zz 13
#define Vv 8185
#define G4 764      // 4*H
#define NP 768      // padded 4H (gate-interleaved)
#define VP 8192     // padded V
#define KC 48       // k per chunk in lstm split-K
#define START_TOK 19

// -------- persistent device scratch (no allocations allowed) --------
__device__ float g_h[2][Bz * Hh];
__device__ float g_c[Bz * Hh];
__device__ unsigned long long g_amax[2][Bz];
__device__ float g_encx[Bz * Tt * G4];   // encoder input projections (+bias), PG layout
__device__ float g_decp[Vv * G4];        // vocab decoder projections (+bias), PG layout
__device__ float g_wk1[354 * NP];        // inf_k, PG, padded K rows (353 valid + 1 zero)
__device__ float g_wk2[354 * NP];        // gen_k
__device__ float g_wr1[192 * NP];        // inf_rk, PG, padded (191 valid + 1 zero)
__device__ float g_wr2[192 * NP];        // gen_rk
__device__ float g_wlog[192 * VP];       // out_w, padded cols + 1 zero K row

// -------- helpers --------
__device__ __forceinline__ float sigf(float x) { return 1.f / (1.f + expf(-x)); }

__device__ __forceinline__ void ffma2(unsigned long long& d, unsigned long long a,
                                      unsigned long long b) {
    asm("fma.rn.f32x2 %0, %1, %2, %3;" : "=l"(d) : "l"(a), "l"(b), "l"(d));
}
__device__ __forceinline__ void addf2(unsigned long long& d, unsigned long long a,
                                      unsigned long long b) {
    asm("add.rn.f32x2 %0, %1, %2;" : "=l"(d) : "l"(a), "l"(b));
}
__device__ __forceinline__ unsigned long long dup2(float x) {
    unsigned long long r;
    asm("mov.b64 %0, {%1, %1};" : "=l"(r) : "f"(x));
    return r;
}
__device__ __forceinline__ float2 unpk(unsigned long long v) {
    float2 r;
    asm("mov.b64 {%0, %1}, %2;" : "=f"(r.x), "=f"(r.y) : "l"(v));
    return r;
}

// -------- setup: zero state + all weight permutes (one kernel) --------
#define N_A (Bz * Hh)
#define N_K (354 * NP)
#define N_R (192 * NP)
#define N_V (192 * VP)
#define N_SETUP (N_A + 2 * N_K + 2 * N_R + N_V)

__global__ void setup_kernel(const float* __restrict__ inf_k, const float* __restrict__ gen_k,
                             const float* __restrict__ inf_rk, const float* __restrict__ gen_rk,
                             const float* __restrict__ out_w)
{
    int i = blockIdx.x * 256 + threadIdx.x;
    if (i < N_A) { g_h[0][i] = 0.f; g_c[i] = 0.f; return; }
    i -= N_A;
    if (i < N_K) {
        int k = i / NP, n = i - k * NP;
        g_wk1[i] = (n < G4 && k < Ee) ? inf_k[k * G4 + (n & 3) * Hh + (n >> 2)] : 0.f;
        return;
    }
    i -= N_K;
    if (i < N_K) {
        int k = i / NP, n = i - k * NP;
        g_wk2[i] = (n < G4 && k < Ee) ? gen_k[k * G4 + (n & 3) * Hh + (n >> 2)] : 0.f;
        return;
    }
    i -= N_K;
    if (i < N_R) {
        int k = i / NP, n = i - k * NP;
        g_wr1[i] = (n < G4 && k < Hh) ? inf_rk[k * G4 + (n & 3) * Hh + (n >> 2)] : 0.f;
        return;
    }
    i -= N_R;
    if (i < N_R) {
        int k = i / NP, n = i - k * NP;
        g_wr2[i] = (n < G4 && k < Hh) ? gen_rk[k * G4 + (n & 3) * Hh + (n >> 2)] : 0.f;
        return;
    }
    i -= N_R;
    if (i < N_V) {
        int k = i >> 13, v = i & (VP - 1);
        g_wlog[i] = (v < Vv && k < Hh) ? out_w[k * Vv + v] : 0.f;
    }
}

// -------- input projection GEMM (gathered rows), FFMA2, manual depth-2 prefetch ----
__global__ __launch_bounds__(256) void proj_kernel(
    const int* __restrict__ idx, int M,
    const float* __restrict__ emb,
    const float* __restrict__ Wpg,    // [354][NP]
    const float* __restrict__ bias,   // [G4] original gate-block order
    float* __restrict__ outp)         // [M][G4]
{
    __shared__ float A[32][356];
    int tid = threadIdx.x, cc = tid & 31, rr = tid >> 5;
    int c0 = blockIdx.x * 256, r0 = blockIdx.y * 32;

    for (int i = tid; i < 32 * 354; i += 256) {
        int r = i / 354, k = i - r * 354;
        int m = r0 + r;
        int tok = (m < M) ? (idx ? idx[m] : m) : 0;
        A[r][k] = (k < Ee) ? emb[tok * Ee + k] : 0.f;
    }
    __syncthreads();

    int ca = c0 + cc * 4, cb = ca + 128;
    unsigned long long acc[4][4];
#pragma unroll
    for (int r = 0; r < 4; r++)
#pragma unroll
        for (int q = 0; q < 4; q++) acc[r][q] = 0ull;

    const int S = NP / 4;
    const ulonglong2* wa = (const ulonglong2*)(Wpg + ca);
    const ulonglong2* wb = (const ulonglong2*)(Wpg + cb);
    ulonglong2 a0 = wa[0], b0 = wb[0];
    ulonglong2 a1 = wa[S], b1 = wb[S];
    for (int k = 0; k < 354; k += 2) {
        int n0 = k + 2 < 354 ? k + 2 : 352;
        int n1 = k + 3 < 354 ? k + 3 : 353;
        ulonglong2 na0 = wa[n0 * S], nb0 = wb[n0 * S];
        ulonglong2 na1 = wa[n1 * S], nb1 = wb[n1 * S];
#pragma unroll
        for (int r = 0; r < 4; r++) {
            unsigned long long h0 = dup2(A[rr + 8 * r][k]);
            ffma2(acc[r][0], h0, a0.x); ffma2(acc[r][1], h0, a0.y);
            ffma2(acc[r][2], h0, b0.x); ffma2(acc[r][3], h0, b0.y);
            unsigned long long h1 = dup2(A[rr + 8 * r][k + 1]);
            ffma2(acc[r][0], h1, a1.x); ffma2(acc[r][1], h1, a1.y);
            ffma2(acc[r][2], h1, b1.x); ffma2(acc[r][3], h1, b1.y);
        }
        a0 = na0; b0 = nb0; a1 = na1; b1 = nb1;
    }

    int ja = ca >> 2, jb = cb >> 2;
    bool cbok = (jb < Hh);
    float ba[4], bb[4];
#pragma unroll
    for (int g = 0; g < 4; g++) {
        ba[g] = bias[g * Hh + ja];
        bb[g] = cbok ? bias[g * Hh + jb] : 0.f;
    }
#pragma unroll
    for (int r = 0; r < 4; r++) {
        int m = r0 + rr + 8 * r;
        if (m >= M) continue;
        float* op = outp + (size_t)m * G4;
        float2 v01 = unpk(acc[r][0]), v23 = unpk(acc[r][1]);
        float2 v45 = unpk(acc[r][2]), v67 = unpk(acc[r][3]);
        float4 va = make_float4(v01.x + ba[0], v01.y + ba[1], v23.x + ba[2], v23.y + ba[3]);
        *(float4*)(op + ca) = va;
        if (cbok) {
            float4 vb = make_float4(v45.x + bb[0], v45.y + bb[1], v67.x + bb[2], v67.y + bb[3]);
            *(float4*)(op + cb) = vb;
        }
    }
}

// -------- LSTM recurrent step v3: split-K within the CTA --------
// 256 threads = 32 units x (4 k-chunks x 2 row-groups). Thread: 4 rows, 48 ks,
// manual depth-4 prefetch. Phase 2: 32 units x 8 rows, reduce + activations.
// grid (6, 32).
__global__ __launch_bounds__(256) void lstm_step(
    const float* __restrict__ Wpg,      // [192][NP]
    const float* __restrict__ h_prev,
    float* __restrict__ h_new,
    const float* __restrict__ pre_base,
    int t, int mode,
    const unsigned long long* __restrict__ amax_in,
    unsigned long long* __restrict__ amax_out)
{
    __shared__ unsigned long long hs[8][192];          // h duplicated as f32x2
    __shared__ unsigned long long part[4][8][32][3];   // [kc][row][unit][2 used + pad]
    int tid = threadIdx.x;
    int u = tid & 31;
    int w = tid >> 5;
    int kc = w & 3, rw = w >> 2;
    int u0 = blockIdx.x * 32, r0 = blockIdx.y * 8;
    int j = u0 + u;
    int jc = j < Hh ? j : Hh - 1;

    if (mode && blockIdx.x == 0 && tid < 8) amax_out[r0 + tid] = 0ull;

    // phase-2 identity prefetches (p, c) — hidden behind phase 1
    int r2 = tid >> 5;
    int row2 = r0 + r2;
    float4 p;
    {
        const float* pb;
        if (mode == 0)      pb = pre_base + ((size_t)row2 * Tt + t) * G4;
        else if (mode == 1) pb = pre_base + (size_t)START_TOK * G4;
        else {
            int tok = Vv - 1 - (int)(unsigned)(amax_in[row2] & 0xFFFFFFFFull);
            pb = pre_base + (size_t)tok * G4;
        }
        p = *(const float4*)(pb + 4 * jc);
    }
    float cp = g_c[row2 * Hh + jc];

    // stage h (duplicated)
    for (int i = tid; i < 8 * 192; i += 256) {
        int r = i / 192, k = i - r * 192;
        float v = (k < Hh) ? h_prev[(r0 + r) * Hh + k] : 0.f;
        hs[r][k] = dup2(v);
    }
    __syncthreads();

    // phase 1: partial gates over k-chunk kc for rows rbase..rbase+3
    int rbase = rw * 4;
    int k0 = kc * KC;
    unsigned long long acc[4][2];
#pragma unroll
    for (int r = 0; r < 4; r++) { acc[r][0] = 0ull; acc[r][1] = 0ull; }

    const ulonglong2* wp = (const ulonglong2*)(Wpg + (size_t)k0 * NP + j * 4);
    ulonglong2 wc[4];
#pragma unroll
    for (int q = 0; q < 4; q++) wc[q] = wp[q * (NP / 4)];
#pragma unroll
    for (int kk = 0; kk < KC; kk += 4) {
        ulonglong2 wn[4];
#pragma unroll
        for (int q = 0; q < 4; q++) {
            int nk = kk + 4 + q;
            if (nk > KC - 1) nk = KC - 1;
            wn[q] = wp[nk * (NP / 4)];
        }
#pragma unroll
        for (int q = 0; q < 4; q++) {
            int k = k0 + kk + q;
#pragma unroll
            for (int r = 0; r < 4; r++) {
                unsigned long long hv = hs[rbase + r][k];
                ffma2(acc[r][0], hv, wc[q].x);
                ffma2(acc[r][1], hv, wc[q].y);
            }
        }
#pragma unroll
        for (int q = 0; q < 4; q++) wc[q] = wn[q];
    }
#pragma unroll
    for (int r = 0; r < 4; r++) {
        part[kc][rbase + r][u][0] = acc[r][0];
        part[kc][rbase + r][u][1] = acc[r][1];
    }
    __syncthreads();

    // phase 2: reduce 4 k-chunks (fixed order), activations, state update
    if (j < Hh) {
        unsigned long long s0 = part[0][r2][u][0];
        unsigned long long s1 = part[0][r2][u][1];
#pragma unroll
        for (int q = 1; q < 4; q++) {
            addf2(s0, s0, part[q][r2][u][0]);
            addf2(s1, s1, part[q][r2][u][1]);
        }
        float2 g01 = unpk(s0), g23 = unpk(s1);
        float iv = sigf(g01.x + p.x);
        float fv = sigf(g01.y + p.y);
        float gv = tanhf(g23.x + p.z);
        float ov = sigf(g23.y + p.w);
        float cn = fv * cp + iv * gv;
        g_c[row2 * Hh + j] = cn;
        h_new[row2 * Hh + j] = ov * tanhf(cn);
    }
}

// -------- latent head --------
__global__ void latent_kernel(const float* __restrict__ h_enc, const float* __restrict__ eps,
                              const float* __restrict__ mu_w, const float* __restrict__ mu_b,
                              const float* __restrict__ sig_w, const float* __restrict__ sig_b,
                              const float* __restrict__ init_w, const float* __restrict__ init_b,
                              float* __restrict__ h_dec)
{
    __shared__ float hrow[Hh];
    __shared__ float z_s[Zz];
    int b = blockIdx.x, tid = threadIdx.x;
    if (tid < Hh) hrow[tid] = h_enc[b * Hh + tid];
    __syncthreads();
    if (tid < Zz) {
        float mu = mu_b[tid], sg = sig_b[tid];
        for (int k = 0; k < Hh; k++) {
            mu = fmaf(hrow[k], mu_w[k * Zz + tid], mu);
            sg = fmaf(hrow[k], sig_w[k * Zz + tid], sg);
        }
        z_s[tid] = mu + eps[tid] * sg;
    }
    __syncthreads();
    if (tid < Hh) {
        float v = init_b[tid];
#pragma unroll
        for (int z = 0; z < Zz; z++) v = fmaf(z_s[z], init_w[z * Hh + tid], v);
        h_dec[b * Hh + tid] = v;
        g_c[b * Hh + tid] = v;
    }
}

// -------- logits GEMM + fused argmax v3 --------
// tile 32 rows x 256 cols; 256 threads = 32 col-threads x 8 row-threads, 4 rows each.
// grid (32, 8) = 256 CTAs. Manual depth-2 two-stream prefetch.
__global__ __launch_bounds__(256) void logits_kernel(
    const float* __restrict__ hsrc,
    const float* __restrict__ W,      // [192][VP]
    const float* __restrict__ bo,
    float* __restrict__ out, int t,
    unsigned long long* __restrict__ amax)
{
    __shared__ unsigned long long hs[32][192];
    int tid = threadIdx.x, cc = tid & 31, rr = tid >> 5;
    int c0 = blockIdx.x * 256, r0 = blockIdx.y * 32;

    for (int i = tid; i < 32 * 192; i += 256) {
        int r = i / 192, k = i - r * 192;
        float v = (k < Hh) ? hsrc[(r0 + r) * Hh + k] : 0.f;
        hs[r][k] = dup2(v);
    }
    __syncthreads();

    int ca = c0 + cc * 4, cb = ca + 128;
    unsigned long long acc[4][4];
#pragma unroll
    for (int r = 0; r < 4; r++)
#pragma unroll
        for (int q = 0; q < 4; q++) acc[r][q] = 0ull;

    const int S = VP / 4;
    const ulonglong2* wa = (const ulonglong2*)(W + ca);
    const ulonglong2* wb = (const ulonglong2*)(W + cb);
    ulonglong2 a0 = wa[0], b0 = wb[0];
    ulonglong2 a1 = wa[S], b1 = wb[S];
    for (int k = 0; k < 192; k += 2) {
        int n0 = k + 2 < 192 ? k + 2 : 190;
        int n1 = k + 3 < 192 ? k + 3 : 191;
        ulonglong2 na0 = wa[n0 * S], nb0 = wb[n0 * S];
        ulonglong2 na1 = wa[n1 * S], nb1 = wb[n1 * S];
#pragma unroll
        for (int r = 0; r < 4; r++) {
            unsigned long long h0 = hs[rr + 8 * r][k];
            ffma2(acc[r][0], h0, a0.x); ffma2(acc[r][1], h0, a0.y);
            ffma2(acc[r][2], h0, b0.x); ffma2(acc[r][3], h0, b0.y);
            unsigned long long h1 = hs[rr + 8 * r][k + 1];
            ffma2(acc[r][0], h1, a1.x); ffma2(acc[r][1], h1, a1.y);
            ffma2(acc[r][2], h1, b1.x); ffma2(acc[r][3], h1, b1.y);
        }
        a0 = na0; b0 = nb0; a1 = na1; b1 = nb1;
    }

    float ba0 = bo[ca], ba1 = bo[ca + 1], ba2 = bo[ca + 2], ba3 = bo[ca + 3];
    float bb0 = (cb < Vv) ? bo[cb] : 0.f;
    float bb1 = (cb + 1 < Vv) ? bo[cb + 1] : 0.f;
    float bb2 = (cb + 2 < Vv) ? bo[cb + 2] : 0.f;
    float bb3 = (cb + 3 < Vv) ? bo[cb + 3] : 0.f;

#pragma unroll
    for (int r = 0; r < 4; r++) {
        int row = r0 + rr + 8 * r;
        float* orow = out + ((size_t)row * Tt + t) * Vv;
        float2 v01 = unpk(acc[r][0]), v23 = unpk(acc[r][1]);
        float2 v45 = unpk(acc[r][2]), v67 = unpk(acc[r][3]);
        float v[8];
        v[0] = v01.x + ba0; v[1] = v01.y + ba1; v[2] = v23.x + ba2; v[3] = v23.y + ba3;
        v[4] = v45.x + bb0; v[5] = v45.y + bb1; v[6] = v67.x + bb2; v[7] = v67.y + bb3;

        orow[ca] = v[0]; orow[ca + 1] = v[1]; orow[ca + 2] = v[2]; orow[ca + 3] = v[3];
        if (cb < Vv)     orow[cb]     = v[4];
        if (cb + 1 < Vv) orow[cb + 1] = v[5];
        if (cb + 2 < Vv) orow[cb + 2] = v[6];
        if (cb + 3 < Vv) orow[cb + 3] = v[7];

        unsigned long long key = 0ull;
#pragma unroll
        for (int g = 0; g < 8; g++) {
            int col = (g < 4) ? ca + g : cb + g - 4;
            unsigned long long kk2 = 0ull;
            if (col < Vv) {
                unsigned u_ = __float_as_uint(v[g]);
                unsigned m = (u_ & 0x80000000u) ? ~u_ : (u_ | 0x80000000u);
                kk2 = ((unsigned long long)m << 32) | (unsigned)(Vv - 1 - col);
            }
            key = (kk2 > key) ? kk2 : key;
        }
#pragma unroll
        for (int s = 16; s > 0; s >>= 1) {
            unsigned long long o = __shfl_xor_sync(0xFFFFFFFFu, key, s);
            key = (o > key) ? o : key;
        }
        if (cc == 0) atomicMax(&amax[row], key);
    }
}

// -------- host orchestration --------
extern "C" void kernel_launch(void* const* d_in, const int* in_sizes, int n_in,
                              void* d_out, int out_size)
{
    const int*   inputs = (const int*)  d_in[0];
    const float* eps    = (const float*)d_in[1];
    const float* emb    = (const float*)d_in[2];
    const float* inf_k  = (const float*)d_in[3];
    const float* inf_rk = (const float*)d_in[4];
    const float* inf_b  = (const float*)d_in[5];
    const float* mu_w   = (const float*)d_in[6];
    const float* mu_b   = (const float*)d_in[7];
    const float* sig_w  = (const float*)d_in[8];
    const float* sig_b  = (const float*)d_in[9];
    const float* init_w = (const float*)d_in[10];
    const float* init_b = (const float*)d_in[11];
    const float* gen_k  = (const float*)d_in[12];
    const float* gen_rk = (const float*)d_in[13];
    const float* gen_b  = (const float*)d_in[14];
    const float* out_w  = (const float*)d_in[15];
    const float* out_b  = (const float*)d_in[16];
    float* out = (float*)d_out;

    float *hbase, *encx, *decp, *wk1, *wk2, *wr1, *wr2, *wlog;
    unsigned long long* ambase;
    cudaGetSymbolAddress((void**)&hbase,  g_h);
    cudaGetSymbolAddress((void**)&encx,   g_encx);
    cudaGetSymbolAddress((void**)&decp,   g_decp);
    cudaGetSymbolAddress((void**)&wk1,    g_wk1);
    cudaGetSymbolAddress((void**)&wk2,    g_wk2);
    cudaGetSymbolAddress((void**)&wr1,    g_wr1);
    cudaGetSymbolAddress((void**)&wr2,    g_wr2);
    cudaGetSymbolAddress((void**)&wlog,   g_wlog);
    cudaGetSymbolAddress((void**)&ambase, g_amax);

    float* hbuf[2] = {hbase, hbase + Bz * Hh};
    unsigned long long* am[2] = {ambase, ambase + Bz};

    setup_kernel<<<(N_SETUP + 255) / 256, 256>>>(inf_k, gen_k, inf_rk, gen_rk, out_w);
    proj_kernel<<<dim3(3, (Bz * Tt + 31) / 32), 256>>>(inputs, Bz * Tt, emb, wk1, inf_b, encx);
    proj_kernel<<<dim3(3, (Vv + 31) / 32), 256>>>(nullptr, Vv, emb, wk2, gen_b, decp);

    dim3 lgrid(6, 32);    // 6 unit tiles (192) x 32 row tiles (256)
    dim3 ogrid(32, 8);    // 32 v tiles (8192) x 8 row tiles (256)

    // ----- encoder -----
    int cur = 0;
    for (int t = 0; t < Tt; t++) {
        lstm_step<<<lgrid, 256>>>(wr1, hbuf[cur], hbuf[cur ^ 1], encx, t, 0,
                                  nullptr, nullptr);
        cur ^= 1;
    }

    // ----- latent -----
    latent_kernel<<<Bz, 192>>>(hbuf[cur], eps, mu_w, mu_b, sig_w, sig_b,
                               init_w, init_b, hbuf[cur ^ 1]);
    cur ^= 1;

    // ----- autoregressive decoder -----
    for (int t = 0; t < Tt; t++) {
        int p = t & 1;
        lstm_step<<<lgrid, 256>>>(wr2, hbuf[cur], hbuf[cur ^ 1], decp, t,
                                  (t == 0) ? 1 : 2, am[p ^ 1], am[p]);
        cur ^= 1;
        logits_kernel<<<ogrid, 256>>>(hbuf[cur], wlog, out_b, out, t, am[p]);
    }
}